// round 1
// baseline (speedup 1.0000x reference)
#include <cuda_runtime.h>
#include <math.h>

#define H 1024
#define L 128
#define V 50257

// ---- scratch (device globals; no allocation allowed) ----
__device__ __align__(16) float g_attn_logits[L];
__device__ __align__(16) float g_attn_w[L];
__device__ __align__(16) float g_with_attn[H];
__device__ __align__(16) float g_rnn_in[H];
__device__ __align__(16) float g_hnew[H];
__device__ __align__(16) float g_logits[V];
__device__ unsigned int g_max_enc;   // ordered-uint encoded max
__device__ float g_sumexp;

__device__ __forceinline__ float warp_sum(float v) {
#pragma unroll
    for (int o = 16; o > 0; o >>= 1) v += __shfl_xor_sync(0xffffffffu, v, o);
    return v;
}

__device__ __forceinline__ float dot4(float4 a, float4 b) {
    return a.x * b.x + a.y * b.y + a.z * b.z + a.w * b.w;
}

// encode float so unsigned compare == float compare
__device__ __forceinline__ unsigned int enc_f(float f) {
    unsigned int u = __float_as_uint(f);
    return (u & 0x80000000u) ? ~u : (u | 0x80000000u);
}
__device__ __forceinline__ float dec_f(unsigned int u) {
    return (u & 0x80000000u) ? __uint_as_float(u ^ 0x80000000u)
                             : __uint_as_float(~u);
}

// ---- K1: attention logits[l] = dot(attn_W[l], [emb[x], h0]) + attn_b[l] ----
__global__ void k_attn_logits(const int* __restrict__ x,
                              const float* __restrict__ hidden,
                              const float* __restrict__ emb,
                              const float* __restrict__ attn_W,
                              const float* __restrict__ attn_b) {
    int l = blockIdx.x;          // 0..127
    int t = threadIdx.x;         // 0..255, each covers 8 contiguous j
    const float* erow = emb + (long long)x[0] * H;
    const float* wrow = attn_W + (long long)l * 2 * H;
    int j0 = t * 8;
    const float* cat = (j0 < H) ? erow : (hidden - H);
    float acc = 0.f;
#pragma unroll
    for (int jj = 0; jj < 8; jj += 4) {
        float4 w = *(const float4*)(wrow + j0 + jj);
        float4 c = *(const float4*)(cat + j0 + jj);
        acc += dot4(w, c);
    }
    acc = warp_sum(acc);
    __shared__ float s[8];
    if ((t & 31) == 0) s[t >> 5] = acc;
    __syncthreads();
    if (t < 8) {
        float v = s[t];
#pragma unroll
        for (int o = 4; o > 0; o >>= 1) v += __shfl_xor_sync(0xffu, v, o);
        if (t == 0) g_attn_logits[l] = v + attn_b[l];
    }
}

// ---- K2: softmax over 128 logits; also reset atomics for this replay ----
__global__ void k_attn_softmax(float* __restrict__ out_attn) {
    int t = threadIdx.x;  // 128 threads
    float v = g_attn_logits[t];
    __shared__ float redm[4], reds[4];
    float m = v;
#pragma unroll
    for (int o = 16; o > 0; o >>= 1) m = fmaxf(m, __shfl_xor_sync(0xffffffffu, m, o));
    if ((t & 31) == 0) redm[t >> 5] = m;
    __syncthreads();
    float m4 = fmaxf(fmaxf(redm[0], redm[1]), fmaxf(redm[2], redm[3]));
    float e = expf(v - m4);
    float s = warp_sum(e);
    if ((t & 31) == 0) reds[t >> 5] = s;
    __syncthreads();
    float tot = reds[0] + reds[1] + reds[2] + reds[3];
    float w = e / tot;
    g_attn_w[t] = w;
    out_attn[t] = w;
    if (t == 0) { g_max_enc = 0u; g_sumexp = 0.f; }
}

// ---- K3: with_attn[h] = sum_l w[l] * enc[l, h] ----
__global__ void k_with_attn(const float* __restrict__ enc) {
    __shared__ float w[L];
    int t = threadIdx.x;
    if (t < L) w[t] = g_attn_w[t];
    __syncthreads();
    int col = blockIdx.x * 256 + t;
    float acc = 0.f;
#pragma unroll 4
    for (int l = 0; l < L; l++) acc += w[l] * enc[l * H + col];
    g_with_attn[col] = acc;
}

// ---- K4: rnn_in[i] = relu(dot(comb_W[i], [emb[x], with_attn]) + comb_b[i]) ----
// warp per row, 8 warps/block, 128 blocks
__global__ void k_rnn_in(const int* __restrict__ x,
                         const float* __restrict__ emb,
                         const float* __restrict__ comb_W,
                         const float* __restrict__ comb_b) {
    int warp = (blockIdx.x * blockDim.x + threadIdx.x) >> 5;  // row 0..1023
    int lane = threadIdx.x & 31;
    const float* erow = emb + (long long)x[0] * H;
    const float* wrow = comb_W + (long long)warp * 2 * H;
    float acc = 0.f;
#pragma unroll
    for (int k = 0; k < 8; k++) {
        int j = k * 128 + lane * 4;
        float4 w = *(const float4*)(wrow + j);
        float4 c = *(const float4*)(erow + j);
        acc += dot4(w, c);
    }
#pragma unroll
    for (int k = 8; k < 16; k++) {
        int j = k * 128 + lane * 4;
        float4 w = *(const float4*)(wrow + j);
        float4 c = *(const float4*)(g_with_attn + (j - H));
        acc += dot4(w, c);
    }
    acc = warp_sum(acc);
    if (lane == 0) g_rnn_in[warp] = fmaxf(acc + comb_b[warp], 0.f);
}

// ---- K5: GRU cell. block i: 6 warps compute the 6 needed dot products ----
__global__ void k_gru(const float* __restrict__ hidden,
                      const float* __restrict__ W_ih,
                      const float* __restrict__ W_hh,
                      const float* __restrict__ b_ih,
                      const float* __restrict__ b_hh,
                      float* __restrict__ out_h) {
    int i = blockIdx.x;              // hidden index 0..1023
    int w = threadIdx.x >> 5;        // 0..5
    int lane = threadIdx.x & 31;
    int g = (w < 3) ? w : (w - 3);
    const float* row;
    const float* vec;
    if (w < 3) { row = W_ih + (long long)(g * H + i) * H; vec = g_rnn_in; }
    else       { row = W_hh + (long long)(g * H + i) * H; vec = hidden;  }
    float acc = 0.f;
#pragma unroll
    for (int k = 0; k < 8; k++) {
        int j = k * 128 + lane * 4;
        float4 a = *(const float4*)(row + j);
        float4 b = *(const float4*)(vec + j);
        acc += dot4(a, b);
    }
    acc = warp_sum(acc);
    __shared__ float s[6];
    if (lane == 0) s[w] = acc + ((w < 3) ? b_ih[g * H + i] : b_hh[g * H + i]);
    __syncthreads();
    if (threadIdx.x == 0) {
        float r = 1.f / (1.f + expf(-(s[0] + s[3])));
        float z = 1.f / (1.f + expf(-(s[1] + s[4])));
        float n = tanhf(s[2] + r * s[5]);
        float h = (1.f - z) * n + z * hidden[i];
        g_hnew[i] = h;
        out_h[i] = h;
    }
}

// ---- K6: big vocab GEMV. warp per row, grid-stride; h cached in registers ----
__global__ void __launch_bounds__(256) k_logits(const float* __restrict__ out_W,
                                                const float* __restrict__ out_b) {
    int lane = threadIdx.x & 31;
    int warp = (blockIdx.x * blockDim.x + threadIdx.x) >> 5;
    int nwarps = (gridDim.x * blockDim.x) >> 5;
    float4 h[8];
#pragma unroll
    for (int k = 0; k < 8; k++)
        h[k] = *(const float4*)(g_hnew + k * 128 + lane * 4);
    float lmax = -INFINITY;
    for (int v = warp; v < V; v += nwarps) {
        const float* row = out_W + (long long)v * H;
        float acc = 0.f;
#pragma unroll
        for (int k = 0; k < 8; k++) {
            float4 a = *(const float4*)(row + k * 128 + lane * 4);
            acc += dot4(a, h[k]);
        }
        acc = warp_sum(acc);
        if (lane == 0) {
            float lg = acc + out_b[v];
            g_logits[v] = lg;
            lmax = fmaxf(lmax, lg);
        }
    }
    if (lane == 0 && lmax > -INFINITY) {
        atomicMax(&g_max_enc, enc_f(lmax));
    }
}

// ---- K7: sum of exp(logit - max) ----
__global__ void k_sumexp() {
    float gmax = dec_f(g_max_enc);
    int idx = blockIdx.x * blockDim.x + threadIdx.x;
    int stride = gridDim.x * blockDim.x;
    float s = 0.f;
    for (int v = idx; v < V; v += stride) s += expf(g_logits[v] - gmax);
    s = warp_sum(s);
    __shared__ float red[8];
    if ((threadIdx.x & 31) == 0) red[threadIdx.x >> 5] = s;
    __syncthreads();
    if (threadIdx.x == 0) {
        float t = 0.f;
#pragma unroll
        for (int i = 0; i < 8; i++) t += red[i];
        atomicAdd(&g_sumexp, t);
    }
}

// ---- K8: logp[v] = logit[v] - (max + log(sumexp)) ----
__global__ void k_writeout(float* __restrict__ out) {
    float gmax = dec_f(g_max_enc);
    float lse = gmax + logf(g_sumexp);
    int idx = blockIdx.x * blockDim.x + threadIdx.x;
    int stride = gridDim.x * blockDim.x;
    for (int v = idx; v < V; v += stride) out[v] = g_logits[v] - lse;
}

extern "C" void kernel_launch(void* const* d_in, const int* in_sizes, int n_in,
                              void* d_out, int out_size) {
    const int*   x       = (const int*)d_in[0];
    const float* hidden  = (const float*)d_in[1];
    const float* enc     = (const float*)d_in[2];
    const float* emb     = (const float*)d_in[3];
    const float* attn_W  = (const float*)d_in[4];
    const float* attn_b  = (const float*)d_in[5];
    const float* comb_W  = (const float*)d_in[6];
    const float* comb_b  = (const float*)d_in[7];
    const float* W_ih    = (const float*)d_in[8];
    const float* W_hh    = (const float*)d_in[9];
    const float* b_ih    = (const float*)d_in[10];
    const float* b_hh    = (const float*)d_in[11];
    const float* out_W   = (const float*)d_in[12];
    const float* out_b   = (const float*)d_in[13];
    float* out = (float*)d_out;   // layout: [logp V][h_new H][attn_w L]

    k_attn_logits<<<L, 256>>>(x, hidden, emb, attn_W, attn_b);
    k_attn_softmax<<<1, L>>>(out + V + H);
    k_with_attn<<<H / 256, 256>>>(enc);
    k_rnn_in<<<H / 8, 256>>>(x, emb, comb_W, comb_b);
    k_gru<<<H, 192>>>(hidden, W_ih, W_hh, b_ih, b_hh, out + V);
    k_logits<<<592, 256>>>(out_W, out_b);   // 4 blocks/SM on 148 SMs
    k_sumexp<<<128, 256>>>();
    k_writeout<<<128, 256>>>(out);
}

// round 2
// speedup vs baseline: 1.2314x; 1.2314x over previous
#include <cuda_runtime.h>
#include <math.h>

#define H 1024
#define L 128
#define V 50257

// ---- scratch (device globals; no allocation allowed) ----
__device__ __align__(16) float g_attn_logits[L];
__device__ __align__(16) float g_attn_w[L];
__device__ __align__(16) float g_with_attn[H];
__device__ __align__(16) float g_rnn_in[H];
__device__ __align__(16) float g_hnew[H];
__device__ __align__(16) float g_logits[V];
__device__ unsigned int g_max_enc;   // ordered-uint encoded max
__device__ float g_sumexp;

__device__ __forceinline__ float warp_sum(float v) {
#pragma unroll
    for (int o = 16; o > 0; o >>= 1) v += __shfl_xor_sync(0xffffffffu, v, o);
    return v;
}

__device__ __forceinline__ float dot4(float4 a, float4 b) {
    return a.x * b.x + a.y * b.y + a.z * b.z + a.w * b.w;
}

// encode float so unsigned compare == float compare
__device__ __forceinline__ unsigned int enc_f(float f) {
    unsigned int u = __float_as_uint(f);
    return (u & 0x80000000u) ? ~u : (u | 0x80000000u);
}
__device__ __forceinline__ float dec_f(unsigned int u) {
    return (u & 0x80000000u) ? __uint_as_float(u ^ 0x80000000u)
                             : __uint_as_float(~u);
}

// ---- K1: attention logits[l] = dot(attn_W[l], [emb[x], h0]) + attn_b[l] ----
__global__ void k_attn_logits(const int* __restrict__ x,
                              const float* __restrict__ hidden,
                              const float* __restrict__ emb,
                              const float* __restrict__ attn_W,
                              const float* __restrict__ attn_b) {
    int l = blockIdx.x;          // 0..127
    int t = threadIdx.x;         // 0..255, each covers 8 contiguous j
    const float* erow = emb + (long long)x[0] * H;
    const float* wrow = attn_W + (long long)l * 2 * H;
    int j0 = t * 8;
    const float* cat = (j0 < H) ? erow : (hidden - H);
    float4 w0 = *(const float4*)(wrow + j0);
    float4 c0 = *(const float4*)(cat + j0);
    float4 w1 = *(const float4*)(wrow + j0 + 4);
    float4 c1 = *(const float4*)(cat + j0 + 4);
    float acc = dot4(w0, c0) + dot4(w1, c1);
    acc = warp_sum(acc);
    __shared__ float s[8];
    if ((t & 31) == 0) s[t >> 5] = acc;
    __syncthreads();
    if (t < 8) {
        float v = s[t];
#pragma unroll
        for (int o = 4; o > 0; o >>= 1) v += __shfl_xor_sync(0xffu, v, o);
        if (t == 0) g_attn_logits[l] = v + attn_b[l];
    }
}

// ---- K2: softmax over 128 logits; also reset atomics for this replay ----
__global__ void k_attn_softmax(float* __restrict__ out_attn) {
    int t = threadIdx.x;  // 128 threads
    float v = g_attn_logits[t];
    __shared__ float redm[4], reds[4];
    float m = v;
#pragma unroll
    for (int o = 16; o > 0; o >>= 1) m = fmaxf(m, __shfl_xor_sync(0xffffffffu, m, o));
    if ((t & 31) == 0) redm[t >> 5] = m;
    __syncthreads();
    float m4 = fmaxf(fmaxf(redm[0], redm[1]), fmaxf(redm[2], redm[3]));
    float e = expf(v - m4);
    float s = warp_sum(e);
    if ((t & 31) == 0) reds[t >> 5] = s;
    __syncthreads();
    float tot = reds[0] + reds[1] + reds[2] + reds[3];
    float w = e / tot;
    g_attn_w[t] = w;
    out_attn[t] = w;
    if (t == 0) { g_max_enc = 0u; g_sumexp = 0.f; }
}

// ---- K3: with_attn[h] = sum_l w[l] * enc[l, h] ----
__global__ void k_with_attn(const float* __restrict__ enc) {
    __shared__ float w[L];
    int t = threadIdx.x;
    if (t < L) w[t] = g_attn_w[t];
    __syncthreads();
    int col = blockIdx.x * 256 + t;
    float acc0 = 0.f, acc1 = 0.f, acc2 = 0.f, acc3 = 0.f;
#pragma unroll
    for (int l = 0; l < L; l += 4) {
        acc0 += w[l + 0] * enc[(l + 0) * H + col];
        acc1 += w[l + 1] * enc[(l + 1) * H + col];
        acc2 += w[l + 2] * enc[(l + 2) * H + col];
        acc3 += w[l + 3] * enc[(l + 3) * H + col];
    }
    g_with_attn[col] = (acc0 + acc1) + (acc2 + acc3);
}

// ---- K4: rnn_in[i] = relu(dot(comb_W[i], [emb[x], with_attn]) + comb_b[i]) ----
// BLOCK per row (1024 blocks): 256 threads, each thread 8 contiguous floats.
__global__ void __launch_bounds__(256) k_rnn_in(const int* __restrict__ x,
                                                const float* __restrict__ emb,
                                                const float* __restrict__ comb_W,
                                                const float* __restrict__ comb_b) {
    int row = blockIdx.x;        // 0..1023
    int t = threadIdx.x;         // 0..255
    const float* erow = emb + (long long)x[0] * H;
    const float* wrow = comb_W + (long long)row * 2 * H;
    int j0 = t * 8;
    const float* cat = (j0 < H) ? erow : (g_with_attn - H);
    float4 w0 = *(const float4*)(wrow + j0);
    float4 c0 = *(const float4*)(cat + j0);
    float4 w1 = *(const float4*)(wrow + j0 + 4);
    float4 c1 = *(const float4*)(cat + j0 + 4);
    float acc = dot4(w0, c0) + dot4(w1, c1);
    acc = warp_sum(acc);
    __shared__ float s[8];
    if ((t & 31) == 0) s[t >> 5] = acc;
    __syncthreads();
    if (t < 8) {
        float v = s[t];
#pragma unroll
        for (int o = 4; o > 0; o >>= 1) v += __shfl_xor_sync(0xffu, v, o);
        if (t == 0) g_rnn_in[row] = fmaxf(v + comb_b[row], 0.f);
    }
}

// ---- K5: GRU cell. block i: 12 warps, each computes half of one of the 6 dots ----
__global__ void __launch_bounds__(384) k_gru(const float* __restrict__ hidden,
                                             const float* __restrict__ W_ih,
                                             const float* __restrict__ W_hh,
                                             const float* __restrict__ b_ih,
                                             const float* __restrict__ b_hh,
                                             float* __restrict__ out_h) {
    int i = blockIdx.x;              // hidden index 0..1023
    int w = threadIdx.x >> 5;        // 0..11
    int lane = threadIdx.x & 31;
    int d = w >> 1;                  // dot index 0..5
    int half = w & 1;                // which 512-col half
    int g = (d < 3) ? d : (d - 3);
    const float* row;
    const float* vec;
    if (d < 3) { row = W_ih + (long long)(g * H + i) * H; vec = g_rnn_in; }
    else       { row = W_hh + (long long)(g * H + i) * H; vec = hidden;  }
    int base = half * 512;
    float acc = 0.f;
#pragma unroll
    for (int k = 0; k < 4; k++) {
        int j = base + k * 128 + lane * 4;
        float4 a = *(const float4*)(row + j);
        float4 b = *(const float4*)(vec + j);
        acc += dot4(a, b);
    }
    acc = warp_sum(acc);
    __shared__ float s[12];
    if (lane == 0) s[w] = acc;
    __syncthreads();
    if (threadIdx.x == 0) {
        float d0 = s[0]  + s[1]  + b_ih[0 * H + i];   // ih_r
        float d1 = s[2]  + s[3]  + b_ih[1 * H + i];   // ih_z
        float d2 = s[4]  + s[5]  + b_ih[2 * H + i];   // ih_n
        float d3 = s[6]  + s[7]  + b_hh[0 * H + i];   // hh_r
        float d4 = s[8]  + s[9]  + b_hh[1 * H + i];   // hh_z
        float d5 = s[10] + s[11] + b_hh[2 * H + i];   // hh_n
        float r = 1.f / (1.f + expf(-(d0 + d3)));
        float z = 1.f / (1.f + expf(-(d1 + d4)));
        float n = tanhf(d2 + r * d5);
        float h = (1.f - z) * n + z * hidden[i];
        g_hnew[i] = h;
        out_h[i] = h;
    }
}

// ---- K6: big vocab GEMV. warp per 2 rows, grid-stride; h cached in registers ----
__global__ void __launch_bounds__(256, 2) k_logits(const float* __restrict__ out_W,
                                                   const float* __restrict__ out_b) {
    int lane = threadIdx.x & 31;
    int warp = (blockIdx.x * blockDim.x + threadIdx.x) >> 5;
    int nwarps = (gridDim.x * blockDim.x) >> 5;
    float4 h[8];
#pragma unroll
    for (int k = 0; k < 8; k++)
        h[k] = *(const float4*)(g_hnew + k * 128 + lane * 4);
    float lmax = -INFINITY;
    for (int v0 = warp * 2; v0 < V; v0 += nwarps * 2) {
        const float* row0 = out_W + (long long)v0 * H;
        const float* row1 = row0 + H;
        bool has1 = (v0 + 1 < V);
        float acc0 = 0.f, acc1 = 0.f;
        if (has1) {
#pragma unroll
            for (int k = 0; k < 8; k++) {
                float4 a0 = *(const float4*)(row0 + k * 128 + lane * 4);
                float4 a1 = *(const float4*)(row1 + k * 128 + lane * 4);
                acc0 += dot4(a0, h[k]);
                acc1 += dot4(a1, h[k]);
            }
        } else {
#pragma unroll
            for (int k = 0; k < 8; k++) {
                float4 a0 = *(const float4*)(row0 + k * 128 + lane * 4);
                acc0 += dot4(a0, h[k]);
            }
        }
        acc0 = warp_sum(acc0);
        acc1 = warp_sum(acc1);
        if (lane == 0) {
            float lg0 = acc0 + out_b[v0];
            g_logits[v0] = lg0;
            lmax = fmaxf(lmax, lg0);
            if (has1) {
                float lg1 = acc1 + out_b[v0 + 1];
                g_logits[v0 + 1] = lg1;
                lmax = fmaxf(lmax, lg1);
            }
        }
    }
    if (lane == 0 && lmax > -INFINITY) {
        atomicMax(&g_max_enc, enc_f(lmax));
    }
}

// ---- K7: sum of exp(logit - max) ----
__global__ void k_sumexp() {
    float gmax = dec_f(g_max_enc);
    int idx = blockIdx.x * blockDim.x + threadIdx.x;
    int stride = gridDim.x * blockDim.x;
    float s = 0.f;
    for (int v = idx; v < V; v += stride) s += expf(g_logits[v] - gmax);
    s = warp_sum(s);
    __shared__ float red[8];
    if ((threadIdx.x & 31) == 0) red[threadIdx.x >> 5] = s;
    __syncthreads();
    if (threadIdx.x == 0) {
        float t = 0.f;
#pragma unroll
        for (int i = 0; i < 8; i++) t += red[i];
        atomicAdd(&g_sumexp, t);
    }
}

// ---- K8: logp[v] = logit[v] - (max + log(sumexp)) ----
__global__ void k_writeout(float* __restrict__ out) {
    float gmax = dec_f(g_max_enc);
    float lse = gmax + logf(g_sumexp);
    int idx = blockIdx.x * blockDim.x + threadIdx.x;
    int stride = gridDim.x * blockDim.x;
    for (int v = idx; v < V; v += stride) out[v] = g_logits[v] - lse;
}

extern "C" void kernel_launch(void* const* d_in, const int* in_sizes, int n_in,
                              void* d_out, int out_size) {
    const int*   x       = (const int*)d_in[0];
    const float* hidden  = (const float*)d_in[1];
    const float* enc     = (const float*)d_in[2];
    const float* emb     = (const float*)d_in[3];
    const float* attn_W  = (const float*)d_in[4];
    const float* attn_b  = (const float*)d_in[5];
    const float* comb_W  = (const float*)d_in[6];
    const float* comb_b  = (const float*)d_in[7];
    const float* W_ih    = (const float*)d_in[8];
    const float* W_hh    = (const float*)d_in[9];
    const float* b_ih    = (const float*)d_in[10];
    const float* b_hh    = (const float*)d_in[11];
    const float* out_W   = (const float*)d_in[12];
    const float* out_b   = (const float*)d_in[13];
    float* out = (float*)d_out;   // layout: [logp V][h_new H][attn_w L]

    k_attn_logits<<<L, 256>>>(x, hidden, emb, attn_W, attn_b);
    k_attn_softmax<<<1, L>>>(out + V + H);
    k_with_attn<<<H / 256, 256>>>(enc);
    k_rnn_in<<<H, 256>>>(x, emb, comb_W, comb_b);
    k_gru<<<H, 384>>>(hidden, W_ih, W_hh, b_ih, b_hh, out + V);
    k_logits<<<296, 256>>>(out_W, out_b);   // 2 blocks/SM on 148 SMs
    k_sumexp<<<256, 256>>>();
    k_writeout<<<256, 256>>>(out);
}

// round 3
// speedup vs baseline: 1.4743x; 1.1973x over previous
#include <cuda_runtime.h>
#include <math.h>

#define H 1024
#define L 128
#define V 50257

// ---- scratch (device globals; no allocation allowed) ----
__device__ __align__(16) float g_attn_logits[L];
__device__ __align__(16) float g_attn_w[L];
__device__ __align__(16) float g_with_attn[H];
__device__ __align__(16) float g_rnn_in[H];
__device__ __align__(16) float g_hnew[H];
__device__ __align__(16) float g_logits[V];
__device__ unsigned int g_max_enc;   // ordered-uint encoded max
__device__ float g_sumexp;

__device__ __forceinline__ float warp_sum(float v) {
#pragma unroll
    for (int o = 16; o > 0; o >>= 1) v += __shfl_xor_sync(0xffffffffu, v, o);
    return v;
}

__device__ __forceinline__ float dot4(float4 a, float4 b) {
    return a.x * b.x + a.y * b.y + a.z * b.z + a.w * b.w;
}

// encode float so unsigned compare == float compare
__device__ __forceinline__ unsigned int enc_f(float f) {
    unsigned int u = __float_as_uint(f);
    return (u & 0x80000000u) ? ~u : (u | 0x80000000u);
}
__device__ __forceinline__ float dec_f(unsigned int u) {
    return (u & 0x80000000u) ? __uint_as_float(u ^ 0x80000000u)
                             : __uint_as_float(~u);
}

// ---- K1: attention logits[l] = dot(attn_W[l], [emb[x], h0]) + attn_b[l] ----
// lane-contiguous float4: thread t covers j=t*4 (emb half) and j=1024+t*4 (hidden half)
__global__ void __launch_bounds__(256) k_attn_logits(const int* __restrict__ x,
                              const float* __restrict__ hidden,
                              const float* __restrict__ emb,
                              const float* __restrict__ attn_W,
                              const float* __restrict__ attn_b) {
    int l = blockIdx.x;          // 0..127
    int t = threadIdx.x;         // 0..255
    const float* erow = emb + (long long)x[0] * H;
    const float* wrow = attn_W + (long long)l * 2 * H;
    int j = t * 4;
    float4 w0 = *(const float4*)(wrow + j);
    float4 c0 = *(const float4*)(erow + j);
    float4 w1 = *(const float4*)(wrow + H + j);
    float4 c1 = *(const float4*)(hidden + j);
    float acc = dot4(w0, c0) + dot4(w1, c1);
    acc = warp_sum(acc);
    __shared__ float s[8];
    if ((t & 31) == 0) s[t >> 5] = acc;
    __syncthreads();
    if (t < 8) {
        float v = s[t];
#pragma unroll
        for (int o = 4; o > 0; o >>= 1) v += __shfl_xor_sync(0xffu, v, o);
        if (t == 0) g_attn_logits[l] = v + attn_b[l];
    }
}

// ---- K2: softmax over 128 logits; zero with_attn; reset atomics ----
__global__ void __launch_bounds__(256) k_attn_softmax(float* __restrict__ out_attn) {
    int t = threadIdx.x;  // 0..255
    // zero g_with_attn (atomicAdd target for K3)
    *(float4*)(g_with_attn + t * 4) = make_float4(0.f, 0.f, 0.f, 0.f);
    if (t >= L) {
        if (t == L) { g_max_enc = 0u; g_sumexp = 0.f; }
        return;
    }
    float v = g_attn_logits[t];
    __shared__ float redm[4], reds[4];
    float m = v;
#pragma unroll
    for (int o = 16; o > 0; o >>= 1) m = fmaxf(m, __shfl_xor_sync(0xffffffffu, m, o));
    if ((t & 31) == 0) redm[t >> 5] = m;
    __syncthreads();
    float m4 = fmaxf(fmaxf(redm[0], redm[1]), fmaxf(redm[2], redm[3]));
    float e = expf(v - m4);
    float s = warp_sum(e);
    if ((t & 31) == 0) reds[t >> 5] = s;
    __syncthreads();
    float tot = reds[0] + reds[1] + reds[2] + reds[3];
    float w = e / tot;
    g_attn_w[t] = w;
    out_attn[t] = w;
}

// ---- K3: with_attn[h] += sum over 32-row chunk of w[l]*enc[l,h] ----
// grid (4 col-chunks, 4 row-chunks); atomicAdd partials (fp order varies < 1e-6)
__global__ void __launch_bounds__(256) k_with_attn(const float* __restrict__ enc) {
    int col = blockIdx.x * 256 + threadIdx.x;
    int l0 = blockIdx.y * 32;
    float acc0 = 0.f, acc1 = 0.f, acc2 = 0.f, acc3 = 0.f;
#pragma unroll
    for (int l = l0; l < l0 + 32; l += 4) {
        acc0 += g_attn_w[l + 0] * __ldg(enc + (l + 0) * H + col);
        acc1 += g_attn_w[l + 1] * __ldg(enc + (l + 1) * H + col);
        acc2 += g_attn_w[l + 2] * __ldg(enc + (l + 2) * H + col);
        acc3 += g_attn_w[l + 3] * __ldg(enc + (l + 3) * H + col);
    }
    atomicAdd(&g_with_attn[col], (acc0 + acc1) + (acc2 + acc3));
}

// ---- K4: rnn_in[i] = relu(dot(comb_W[i], [emb[x], with_attn]) + comb_b[i]) ----
// block per row; lane-contiguous float4
__global__ void __launch_bounds__(256) k_rnn_in(const int* __restrict__ x,
                                                const float* __restrict__ emb,
                                                const float* __restrict__ comb_W,
                                                const float* __restrict__ comb_b) {
    int row = blockIdx.x;        // 0..1023
    int t = threadIdx.x;         // 0..255
    const float* erow = emb + (long long)x[0] * H;
    const float* wrow = comb_W + (long long)row * 2 * H;
    int j = t * 4;
    float4 w0 = *(const float4*)(wrow + j);
    float4 c0 = *(const float4*)(erow + j);
    float4 w1 = *(const float4*)(wrow + H + j);
    float4 c1 = *(const float4*)(g_with_attn + j);
    float acc = dot4(w0, c0) + dot4(w1, c1);
    acc = warp_sum(acc);
    __shared__ float s[8];
    if ((t & 31) == 0) s[t >> 5] = acc;
    __syncthreads();
    if (t < 8) {
        float v = s[t];
#pragma unroll
        for (int o = 4; o > 0; o >>= 1) v += __shfl_xor_sync(0xffu, v, o);
        if (t == 0) g_rnn_in[row] = fmaxf(v + comb_b[row], 0.f);
    }
}

// ---- K5: GRU cell. block i: 12 warps, each computes half of one of the 6 dots ----
__global__ void __launch_bounds__(384) k_gru(const float* __restrict__ hidden,
                                             const float* __restrict__ W_ih,
                                             const float* __restrict__ W_hh,
                                             const float* __restrict__ b_ih,
                                             const float* __restrict__ b_hh,
                                             float* __restrict__ out_h) {
    int i = blockIdx.x;              // hidden index 0..1023
    int w = threadIdx.x >> 5;        // 0..11
    int lane = threadIdx.x & 31;
    int d = w >> 1;                  // dot index 0..5
    int half = w & 1;                // which 512-col half
    int g = (d < 3) ? d : (d - 3);
    const float* row;
    const float* vec;
    if (d < 3) { row = W_ih + (long long)(g * H + i) * H; vec = g_rnn_in; }
    else       { row = W_hh + (long long)(g * H + i) * H; vec = hidden;  }
    int base = half * 512;
    float4 a[4], b[4];
#pragma unroll
    for (int k = 0; k < 4; k++) {
        int j = base + k * 128 + lane * 4;
        a[k] = __ldcs((const float4*)(row + j));
        b[k] = *(const float4*)(vec + j);
    }
    float acc = 0.f;
#pragma unroll
    for (int k = 0; k < 4; k++) acc += dot4(a[k], b[k]);
    acc = warp_sum(acc);
    __shared__ float s[12];
    if (lane == 0) s[w] = acc;
    __syncthreads();
    if (threadIdx.x == 0) {
        float d0 = s[0]  + s[1]  + b_ih[0 * H + i];   // ih_r
        float d1 = s[2]  + s[3]  + b_ih[1 * H + i];   // ih_z
        float d2 = s[4]  + s[5]  + b_ih[2 * H + i];   // ih_n
        float d3 = s[6]  + s[7]  + b_hh[0 * H + i];   // hh_r
        float d4 = s[8]  + s[9]  + b_hh[1 * H + i];   // hh_z
        float d5 = s[10] + s[11] + b_hh[2 * H + i];   // hh_n
        float r = 1.f / (1.f + expf(-(d0 + d3)));
        float z = 1.f / (1.f + expf(-(d1 + d4)));
        float n = tanhf(d2 + r * d5);
        float h = (1.f - z) * n + z * hidden[i];
        g_hnew[i] = h;
        out_h[i] = h;
    }
}

// ---- K6: big vocab GEMV. warp per 2 rows; all 16 loads batched for MLP ----
__global__ void __launch_bounds__(256, 2) k_logits(const float* __restrict__ out_W,
                                                   const float* __restrict__ out_b) {
    int lane = threadIdx.x & 31;
    int warp = (blockIdx.x * blockDim.x + threadIdx.x) >> 5;
    int nwarps = (gridDim.x * blockDim.x) >> 5;
    float4 h[8];
#pragma unroll
    for (int k = 0; k < 8; k++)
        h[k] = *(const float4*)(g_hnew + k * 128 + lane * 4);
    float lmax = -INFINITY;
    for (int v0 = warp * 2; v0 < V - 1; v0 += nwarps * 2) {
        const float* row0 = out_W + (long long)v0 * H + lane * 4;
        const float* row1 = row0 + H;
        float4 a0[8], a1[8];
#pragma unroll
        for (int k = 0; k < 8; k++) a0[k] = __ldcs((const float4*)(row0 + k * 128));
#pragma unroll
        for (int k = 0; k < 8; k++) a1[k] = __ldcs((const float4*)(row1 + k * 128));
        float acc0 = 0.f, acc1 = 0.f;
#pragma unroll
        for (int k = 0; k < 8; k++) {
            acc0 += dot4(a0[k], h[k]);
            acc1 += dot4(a1[k], h[k]);
        }
        acc0 = warp_sum(acc0);
        acc1 = warp_sum(acc1);
        if (lane == 0) {
            float lg0 = acc0 + out_b[v0];
            float lg1 = acc1 + out_b[v0 + 1];
            g_logits[v0] = lg0;
            g_logits[v0 + 1] = lg1;
            lmax = fmaxf(lmax, fmaxf(lg0, lg1));
        }
    }
    // tail: last row (V odd) handled by warp 0
    if (warp == 0) {
        int v = V - 1;
        const float* row = out_W + (long long)v * H + lane * 4;
        float acc = 0.f;
#pragma unroll
        for (int k = 0; k < 8; k++)
            acc += dot4(__ldcs((const float4*)(row + k * 128)), h[k]);
        acc = warp_sum(acc);
        if (lane == 0) {
            float lg = acc + out_b[v];
            g_logits[v] = lg;
            lmax = fmaxf(lmax, lg);
        }
    }
    if (lane == 0 && lmax > -INFINITY) {
        atomicMax(&g_max_enc, enc_f(lmax));
    }
}

// ---- K7: sum of exp(logit - max) ----
__global__ void __launch_bounds__(256) k_sumexp() {
    float gmax = dec_f(g_max_enc);
    int idx = blockIdx.x * blockDim.x + threadIdx.x;
    int stride = gridDim.x * blockDim.x;
    float s = 0.f;
    for (int v = idx; v < V; v += stride) s += expf(g_logits[v] - gmax);
    s = warp_sum(s);
    __shared__ float red[8];
    if ((threadIdx.x & 31) == 0) red[threadIdx.x >> 5] = s;
    __syncthreads();
    if (threadIdx.x == 0) {
        float t = 0.f;
#pragma unroll
        for (int i = 0; i < 8; i++) t += red[i];
        atomicAdd(&g_sumexp, t);
    }
}

// ---- K8: logp[v] = logit[v] - (max + log(sumexp)) ----
__global__ void __launch_bounds__(256) k_writeout(float* __restrict__ out) {
    float gmax = dec_f(g_max_enc);
    float lse = gmax + logf(g_sumexp);
    int idx = blockIdx.x * blockDim.x + threadIdx.x;
    int stride = gridDim.x * blockDim.x;
    for (int v = idx; v < V; v += stride) out[v] = g_logits[v] - lse;
}

extern "C" void kernel_launch(void* const* d_in, const int* in_sizes, int n_in,
                              void* d_out, int out_size) {
    const int*   x       = (const int*)d_in[0];
    const float* hidden  = (const float*)d_in[1];
    const float* enc     = (const float*)d_in[2];
    const float* emb     = (const float*)d_in[3];
    const float* attn_W  = (const float*)d_in[4];
    const float* attn_b  = (const float*)d_in[5];
    const float* comb_W  = (const float*)d_in[6];
    const float* comb_b  = (const float*)d_in[7];
    const float* W_ih    = (const float*)d_in[8];
    const float* W_hh    = (const float*)d_in[9];
    const float* b_ih    = (const float*)d_in[10];
    const float* b_hh    = (const float*)d_in[11];
    const float* out_W   = (const float*)d_in[12];
    const float* out_b   = (const float*)d_in[13];
    float* out = (float*)d_out;   // layout: [logp V][h_new H][attn_w L]

    k_attn_logits<<<L, 256>>>(x, hidden, emb, attn_W, attn_b);
    k_attn_softmax<<<1, 256>>>(out + V + H);
    {
        dim3 g(H / 256, 4);
        k_with_attn<<<g, 256>>>(enc);
    }
    k_rnn_in<<<H, 256>>>(x, emb, comb_W, comb_b);
    k_gru<<<H, 384>>>(hidden, W_ih, W_hh, b_ih, b_hh, out + V);
    k_logits<<<296, 256>>>(out_W, out_b);   // 2 blocks/SM on 148 SMs
    k_sumexp<<<256, 256>>>();
    k_writeout<<<256, 256>>>(out);
}